// round 1
// baseline (speedup 1.0000x reference)
#include <cuda_runtime.h>
#include <math.h>

// Problem constants (fixed-shape benchmark)
#define NN 50000
#define HH 16
#define RR 32
#define CC 8
#define EE 1600000

// Scratch (device globals; no allocation allowed)
__device__ float g_cnt[RR * NN];   // per-(rel,dst) edge counts, 6.4 MB
__device__ float g_x[NN * HH];     // layer-1 node features, 3.2 MB

__device__ __forceinline__ void red_add_v4(float* addr, float4 v) {
    asm volatile("red.global.add.v4.f32 [%0], {%1,%2,%3,%4};"
                 :: "l"(addr), "f"(v.x), "f"(v.y), "f"(v.z), "f"(v.w)
                 : "memory");
}

// ---------------------------------------------------------------- init: zero scratch + out
__global__ void k_init(float* __restrict__ out) {
    int total = RR * NN + NN * HH + NN * CC;
    for (int i = blockIdx.x * blockDim.x + threadIdx.x; i < total;
         i += gridDim.x * blockDim.x) {
        if (i < RR * NN)              g_cnt[i] = 0.f;
        else if (i < RR * NN + NN * HH) g_x[i - RR * NN] = 0.f;
        else                          out[i - RR * NN - NN * HH] = 0.f;
    }
}

// ---------------------------------------------------------------- count edges per (rel,dst)
__global__ void k_count(const int* __restrict__ ei, const int* __restrict__ et) {
    int e = blockIdx.x * blockDim.x + threadIdx.x;
    if (e >= EE) return;
    int dst = ei[EE + e];
    int r   = et[e];
    atomicAdd(&g_cnt[r * NN + dst], 1.0f);
}

// ---------------------------------------------------------------- layer 1 scatter
// x[dst] += w1[rel, src] / cnt[rel, dst]
__global__ void k_layer1(const int* __restrict__ ei, const int* __restrict__ et,
                         const float* __restrict__ w1) {
    int e = blockIdx.x * blockDim.x + threadIdx.x;
    if (e >= EE) return;
    int src = ei[e];
    int dst = ei[EE + e];
    int r   = et[e];
    float c   = g_cnt[r * NN + dst];
    float inv = __frcp_rn(fmaxf(c, 1.0f));
    const float4* w = (const float4*)(w1 + ((size_t)r * NN + (size_t)src) * HH);
    float* xp = g_x + dst * HH;
    #pragma unroll
    for (int i = 0; i < 4; i++) {
        float4 v = __ldg(&w[i]);
        v.x *= inv; v.y *= inv; v.z *= inv; v.w *= inv;
        red_add_v4(xp + i * 4, v);
    }
}

// ---------------------------------------------------------------- activation: x = relu(x + root1 + b1)
__global__ void k_act(const float* __restrict__ root1, const float* __restrict__ b1) {
    int i = blockIdx.x * blockDim.x + threadIdx.x;
    if (i >= NN * HH) return;
    float v = g_x[i] + root1[i] + __ldg(&b1[i & (HH - 1)]);
    g_x[i] = fmaxf(v, 0.0f);
}

// ---------------------------------------------------------------- layer 2 scatter
// out[dst] += (x[src] @ w2[rel]) / cnt[rel, dst]
// w2 staged in smem as [hc][rel] with stride 33 -> lanes with random rel hit
// distinct banks (conflict-free), duplicate rels broadcast.
__global__ void k_layer2(const int* __restrict__ ei, const int* __restrict__ et,
                         const float* __restrict__ w2, float* __restrict__ out) {
    __shared__ float sw[HH * CC * 33];  // 128*33 floats = 16.9 KB
    for (int i = threadIdx.x; i < RR * HH * CC; i += blockDim.x) {
        int rel = i >> 7;       // i / 128
        int hc  = i & 127;      // i % 128
        sw[hc * 33 + rel] = w2[i];
    }
    __syncthreads();

    for (int e = blockIdx.x * blockDim.x + threadIdx.x; e < EE;
         e += gridDim.x * blockDim.x) {
        int src = ei[e];
        int dst = ei[EE + e];
        int r   = et[e];
        float inv = __frcp_rn(fmaxf(g_cnt[r * NN + dst], 1.0f));

        const float4* xp = (const float4*)(g_x + src * HH);
        float acc[CC];
        #pragma unroll
        for (int c = 0; c < CC; c++) acc[c] = 0.0f;

        #pragma unroll
        for (int i4 = 0; i4 < 4; i4++) {
            float4 xv = __ldg(&xp[i4]);
            float xs[4] = {xv.x, xv.y, xv.z, xv.w};
            #pragma unroll
            for (int j = 0; j < 4; j++) {
                int h = i4 * 4 + j;
                #pragma unroll
                for (int c = 0; c < CC; c++)
                    acc[c] += xs[j] * sw[(h * CC + c) * 33 + r];
            }
        }
        float4 v0 = make_float4(acc[0] * inv, acc[1] * inv, acc[2] * inv, acc[3] * inv);
        float4 v1 = make_float4(acc[4] * inv, acc[5] * inv, acc[6] * inv, acc[7] * inv);
        red_add_v4(out + dst * CC, v0);
        red_add_v4(out + dst * CC + 4, v1);
    }
}

// ---------------------------------------------------------------- finalize: + x@root2 + b2, log_softmax
__global__ void k_final(const float* __restrict__ root2, const float* __restrict__ b2,
                        float* __restrict__ out) {
    int n = blockIdx.x * blockDim.x + threadIdx.x;
    if (n >= NN) return;
    const float4* xp = (const float4*)(g_x + n * HH);
    float o[CC];
    #pragma unroll
    for (int c = 0; c < CC; c++) o[c] = out[n * CC + c] + __ldg(&b2[c]);

    #pragma unroll
    for (int i4 = 0; i4 < 4; i4++) {
        float4 xv = xp[i4];
        float xs[4] = {xv.x, xv.y, xv.z, xv.w};
        #pragma unroll
        for (int j = 0; j < 4; j++) {
            int h = i4 * 4 + j;
            #pragma unroll
            for (int c = 0; c < CC; c++)
                o[c] += xs[j] * __ldg(&root2[h * CC + c]);
        }
    }
    float m = o[0];
    #pragma unroll
    for (int c = 1; c < CC; c++) m = fmaxf(m, o[c]);
    float s = 0.0f;
    #pragma unroll
    for (int c = 0; c < CC; c++) s += expf(o[c] - m);
    float l = logf(s) + m;
    #pragma unroll
    for (int c = 0; c < CC; c++) out[n * CC + c] = o[c] - l;
}

// ---------------------------------------------------------------- launch
extern "C" void kernel_launch(void* const* d_in, const int* in_sizes, int n_in,
                              void* d_out, int out_size) {
    const int*   ei    = (const int*)  d_in[0];  // [2, E]
    const int*   et    = (const int*)  d_in[1];  // [E]
    const float* w1    = (const float*)d_in[2];  // [R, N, H]
    const float* root1 = (const float*)d_in[3];  // [N, H]
    const float* b1    = (const float*)d_in[4];  // [H]
    const float* w2    = (const float*)d_in[5];  // [R, H, C]
    const float* root2 = (const float*)d_in[6];  // [H, C]
    const float* b2    = (const float*)d_in[7];  // [C]
    float* out = (float*)d_out;                  // [N, C]

    k_init  <<<512, 256>>>(out);
    k_count <<<(EE + 255) / 256, 256>>>(ei, et);
    k_layer1<<<(EE + 255) / 256, 256>>>(ei, et, w1);
    k_act   <<<(NN * HH + 255) / 256, 256>>>(root1, b1);
    k_layer2<<<2048, 256>>>(ei, et, w2, out);
    k_final <<<(NN + 255) / 256, 256>>>(root2, b2, out);
}